// round 1
// baseline (speedup 1.0000x reference)
#include <cuda_runtime.h>

// AntiAliasInterpolation2d: depthwise 13x13 Gaussian, stride 4, zero padding 6.
// Input  [32,3,512,512] f32, weight [3,1,13,13] f32, output [32,3,128,128] f32.
//
// Separable implementation: the 2D kernel is outer(g,g) with g = row6 / sqrt(center),
// recovered exactly from the provided 2D weight. Fused single kernel:
//   - horizontal filter + stride-4 into smem tile h[R][128]
//   - vertical filter + stride-4 from smem to output
// Each CTA: one (n,c) image, 16 output rows.

#define KS   13
#define TH   16                 // output rows per CTA
#define RR   (4 * TH + 9)       // 73 input-space rows needed (after horizontal pass)
#define IW   512
#define IW4  128                // input width in float4
#define OW   128

__global__ __launch_bounds__(256, 4)
void aa_interp_kernel(const float* __restrict__ inp,
                      const float* __restrict__ w,
                      float* __restrict__ out)
{
    __shared__ float sw[16];
    __shared__ float h[RR][OW];

    const int nc   = blockIdx.x;        // 0..95  (n*3 + c)
    const int c    = nc % 3;
    const int oy0  = blockIdx.y * TH;   // first output row of this tile
    const int tid  = threadIdx.x;

    // Recover the exact 1D factor from the 2D weight:
    // k2[i][j] = g1[i]*g1[j]/S  =>  gn[j] = k2[6][j] / sqrt(k2[6][6]) = g1[j]/sqrt(S)
    if (tid < KS) {
        const float center = w[c * 169 + 6 * 13 + 6];
        sw[tid] = w[c * 169 + 6 * 13 + tid] / sqrtf(center);
    }
    __syncthreads();

    float g[KS];
#pragma unroll
    for (int k = 0; k < KS; k++) g[k] = sw[k];

    const float4* in4 = reinterpret_cast<const float4*>(inp) + (size_t)nc * (IW * IW / 4);
    const int rbase = oy0 * 4 - 6;      // first input row needed

    // ---- horizontal pass: RR rows x 128 strided outputs into smem ----
    for (int e = tid; e < RR * OW; e += 256) {
        const int r  = e >> 7;
        const int ox = e & 127;
        const int iy = rbase + r;
        float acc = 0.0f;
        if (iy >= 0 && iy < IW) {
            const float4* row = in4 + iy * IW4;
            // taps cover x = 4*ox-6 .. 4*ox+6  ->  float4 indices ox-2 .. ox+1
            float f[16];
#pragma unroll
            for (int q = 0; q < 4; q++) {
                const int qi = ox - 2 + q;
                float4 v = (qi >= 0 && qi < IW4) ? row[qi]
                                                 : make_float4(0.f, 0.f, 0.f, 0.f);
                f[q * 4 + 0] = v.x; f[q * 4 + 1] = v.y;
                f[q * 4 + 2] = v.z; f[q * 4 + 3] = v.w;
            }
#pragma unroll
            for (int k = 0; k < KS; k++) acc = fmaf(g[k], f[k + 2], acc);
        }
        h[r][ox] = acc;
    }
    __syncthreads();

    // ---- vertical pass: TH x 128 outputs ----
    float* outp = out + (size_t)nc * (OW * OW);
    for (int e = tid; e < TH * OW; e += 256) {
        const int oyl = e >> 7;
        const int ox  = e & 127;
        float acc = 0.0f;
#pragma unroll
        for (int k = 0; k < KS; k++) acc = fmaf(g[k], h[4 * oyl + k][ox], acc);
        outp[(size_t)(oy0 + oyl) * OW + ox] = acc;
    }
}

extern "C" void kernel_launch(void* const* d_in, const int* in_sizes, int n_in,
                              void* d_out, int out_size)
{
    const float* inp = (const float*)d_in[0];   // [32,3,512,512]
    const float* wgt = (const float*)d_in[1];   // [3,1,13,13]
    float* out = (float*)d_out;                 // [32,3,128,128]

    dim3 grid(96, 128 / TH);                    // 96 images*channels, 8 row-tiles
    aa_interp_kernel<<<grid, 256>>>(inp, wgt, out);
}

// round 2
// speedup vs baseline: 1.3228x; 1.3228x over previous
#include <cuda_runtime.h>

// AntiAliasInterpolation2d: depthwise 13x13 Gaussian, stride 4, zero pad 6.
// Input [32,3,512,512] f32, weight [3,1,13,13] f32, output [32,3,128,128] f32.
//
// Separable: 2D kernel = outer(g,g), g[j] = k2[6][j]/sqrt(k2[6][6]) (exact).
// g is symmetric (g[k]==g[12-k], bitwise by construction) -> 7 distinct taps.
// Fused: horizontal filter+stride4 -> smem tile h[41][128], then vertical.
// CTA = one (n,c) image x 8 output rows. Warp-per-row mapping, float4 I/O.

#define KS   13
#define TH   8                   // output rows per CTA
#define RR   (4 * TH + 9)        // 41 input rows needed
#define IW   512
#define IW4  128                 // input row in float4
#define OW   128
#define OW4  32                  // output row in float4

__global__ __launch_bounds__(256, 6)
void aa_interp_kernel(const float* __restrict__ inp,
                      const float* __restrict__ w,
                      float* __restrict__ out)
{
    __shared__ float  sw[8];
    __shared__ float4 h[RR][OW4];       // 41*32*16 = 20992 B

    const int nc   = blockIdx.x;        // n*3 + c
    const int c    = nc % 3;
    const int oy0  = blockIdx.y * TH;
    const int tid  = threadIdx.x;
    const int lane = tid & 31;
    const int wid  = tid >> 5;

    // 1D factor from 2D weight: gn[j] = k2[6][j] / sqrt(k2[6][6]); symmetric.
    if (tid < 7) {
        const float center = w[c * 169 + 84];          // [6][6]
        sw[tid] = w[c * 169 + 78 + tid] / sqrtf(center); // row 6, taps 0..6
    }
    __syncthreads();

    float g[7];
#pragma unroll
    for (int k = 0; k < 7; k++) g[k] = sw[k];

    const float4* in4 = reinterpret_cast<const float4*>(inp)
                      + (size_t)nc * (IW * IW4);
    const int rbase = oy0 * 4 - 6;

    // ---- horizontal pass: warp w does rows w, w+8, ... ----
    for (int r = wid; r < RR; r += 8) {
        const int iy = rbase + r;
        float* hrow = reinterpret_cast<float*>(&h[r][0]);
        if (iy >= 0 && iy < IW) {
            const float4* row = in4 + (size_t)iy * IW4;
#pragma unroll
            for (int j = 0; j < 4; j++) {
                const int ox = lane + 32 * j;
                float f[16];
#pragma unroll
                for (int q = 0; q < 4; q++) {
                    const int qi = ox - 2 + q;
                    float4 v = (qi >= 0 && qi < IW4) ? row[qi]
                                                     : make_float4(0.f,0.f,0.f,0.f);
                    f[4*q+0] = v.x; f[4*q+1] = v.y;
                    f[4*q+2] = v.z; f[4*q+3] = v.w;
                }
                // taps at f[2..14]; symmetric pairs around f[8]
                float acc = g[6] * f[8];
#pragma unroll
                for (int k = 0; k < 6; k++)
                    acc = fmaf(g[k], f[k + 2] + f[14 - k], acc);
                hrow[ox] = acc;
            }
        } else {
#pragma unroll
            for (int j = 0; j < 4; j++) hrow[lane + 32 * j] = 0.f;
        }
    }
    __syncthreads();

    // ---- vertical pass: warp = output row, lane = float4 column ----
    {
        const int oyl = wid;
        float4 acc;
        {
            float4 v = h[4 * oyl + 6][lane];
            acc.x = g[6] * v.x; acc.y = g[6] * v.y;
            acc.z = g[6] * v.z; acc.w = g[6] * v.w;
        }
#pragma unroll
        for (int k = 0; k < 6; k++) {
            float4 a = h[4 * oyl + k][lane];
            float4 b = h[4 * oyl + 12 - k][lane];
            acc.x = fmaf(g[k], a.x + b.x, acc.x);
            acc.y = fmaf(g[k], a.y + b.y, acc.y);
            acc.z = fmaf(g[k], a.z + b.z, acc.z);
            acc.w = fmaf(g[k], a.w + b.w, acc.w);
        }
        float4* op = reinterpret_cast<float4*>(out + (size_t)nc * (OW * OW)
                                                   + (size_t)(oy0 + oyl) * OW);
        op[lane] = acc;
    }
}

extern "C" void kernel_launch(void* const* d_in, const int* in_sizes, int n_in,
                              void* d_out, int out_size)
{
    const float* inp = (const float*)d_in[0];   // [32,3,512,512]
    const float* wgt = (const float*)d_in[1];   // [3,1,13,13]
    float* out = (float*)d_out;                 // [32,3,128,128]

    dim3 grid(96, 128 / TH);                    // 96 images, 16 row-tiles
    aa_interp_kernel<<<grid, 256>>>(inp, wgt, out);
}

// round 3
// speedup vs baseline: 1.6295x; 1.2319x over previous
#include <cuda_runtime.h>

// AntiAliasInterpolation2d: depthwise 13x13 Gaussian, stride 4, zero pad 6.
// Input [32,3,512,512] f32, weight [3,1,13,13] f32, output [32,3,128,128] f32.
//
// Separable: 2D kernel = outer(g,g), g[j] = k2[6][j]/sqrt(k2[6][6]) (exact),
// and g is symmetric: g[k] == g[12-k] -> only 7 distinct taps needed.
// Fused: horizontal filter+stride4 -> smem tile h[41][128], then vertical.
// Horizontal pass streams one float4 block at a time (low register pressure)
// so the kernel fits 32 regs -> 8 CTAs/SM (100% occupancy).

#define TH   8                   // output rows per CTA
#define RR   (4 * TH + 9)        // 41 input rows needed
#define IW   512
#define IW4  128                 // input row in float4
#define OW   128
#define OW4  32                  // output row in float4

__global__ __launch_bounds__(256, 8)
void aa_interp_kernel(const float* __restrict__ inp,
                      const float* __restrict__ w,
                      float* __restrict__ out)
{
    __shared__ float  sw[8];
    __shared__ float4 h[RR][OW4];       // 41*32*16 = 20992 B

    const int nc   = blockIdx.x;        // n*3 + c
    const int c    = nc % 3;
    const int oy0  = blockIdx.y * TH;
    const int tid  = threadIdx.x;
    const int lane = tid & 31;
    const int wid  = tid >> 5;

    // Exact 1D factor from the 2D weight: gn[j] = k2[6][j] / sqrt(k2[6][6]).
    if (tid < 7) {
        const float center = w[c * 169 + 84];            // [6][6]
        sw[tid] = w[c * 169 + 78 + tid] / sqrtf(center); // row 6, taps 0..6
    }
    __syncthreads();

    float g[7];
#pragma unroll
    for (int k = 0; k < 7; k++) g[k] = sw[k];

    const float4* in4 = reinterpret_cast<const float4*>(inp)
                      + (size_t)nc * (IW * IW4);
    const int rbase = oy0 * 4 - 6;

    const float4 z4 = make_float4(0.f, 0.f, 0.f, 0.f);

    // ---- horizontal pass: warp w does rows w, w+8, ... ----
    for (int r = wid; r < RR; r += 8) {
        const int iy = rbase + r;
        float* hrow = reinterpret_cast<float*>(&h[r][0]);
        if (iy >= 0 && iy < IW) {
            const float4* row = in4 + (size_t)iy * IW4;
#pragma unroll
            for (int j = 0; j < 4; j++) {
                const int ox = lane + 32 * j;
                // taps x = 4*ox-6 .. 4*ox+6; block B holds x = 4B..4B+3
                // tap index k = 4*(B-ox) + comp + 2 ; symmetric g[k]==g[12-k]
                float4 v0 = (ox >= 2)       ? row[ox - 2] : z4; // k 0,1 (z,w)
                float4 v1 = (ox >= 1)       ? row[ox - 1] : z4; // k 2..5
                float4 v2 =                   row[ox];          // k 6..9
                float4 v3 = (ox <= IW4 - 2) ? row[ox + 1] : z4; // k 10..12 (x,y,z)

                float acc =      g[0] * v0.z;
                acc = fmaf(g[1], v0.w, acc);
                acc = fmaf(g[2], v1.x, acc);
                acc = fmaf(g[3], v1.y, acc);
                acc = fmaf(g[4], v1.z, acc);
                acc = fmaf(g[5], v1.w, acc);
                acc = fmaf(g[6], v2.x, acc);
                acc = fmaf(g[5], v2.y, acc);   // k7 -> g[12-7]=g[5]
                acc = fmaf(g[4], v2.z, acc);   // k8
                acc = fmaf(g[3], v2.w, acc);   // k9
                acc = fmaf(g[2], v3.x, acc);   // k10
                acc = fmaf(g[1], v3.y, acc);   // k11
                acc = fmaf(g[0], v3.z, acc);   // k12
                hrow[ox] = acc;
            }
        } else {
#pragma unroll
            for (int j = 0; j < 4; j++) hrow[lane + 32 * j] = 0.f;
        }
    }
    __syncthreads();

    // ---- vertical pass: warp = output row, lane = float4 column ----
    {
        const int oyl = wid;
        float4 acc;
        {
            float4 v = h[4 * oyl + 6][lane];
            acc.x = g[6] * v.x; acc.y = g[6] * v.y;
            acc.z = g[6] * v.z; acc.w = g[6] * v.w;
        }
#pragma unroll
        for (int k = 0; k < 6; k++) {
            float4 a = h[4 * oyl + k][lane];
            float4 b = h[4 * oyl + 12 - k][lane];
            acc.x = fmaf(g[k], a.x + b.x, acc.x);
            acc.y = fmaf(g[k], a.y + b.y, acc.y);
            acc.z = fmaf(g[k], a.z + b.z, acc.z);
            acc.w = fmaf(g[k], a.w + b.w, acc.w);
        }
        float4* op = reinterpret_cast<float4*>(out + (size_t)nc * (OW * OW)
                                                   + (size_t)(oy0 + oyl) * OW);
        op[lane] = acc;
    }
}

extern "C" void kernel_launch(void* const* d_in, const int* in_sizes, int n_in,
                              void* d_out, int out_size)
{
    const float* inp = (const float*)d_in[0];   // [32,3,512,512]
    const float* wgt = (const float*)d_in[1];   // [3,1,13,13]
    float* out = (float*)d_out;                 // [32,3,128,128]

    dim3 grid(96, 128 / TH);                    // 96 images, 16 row-tiles
    aa_interp_kernel<<<grid, 256>>>(inp, wgt, out);
}